// round 4
// baseline (speedup 1.0000x reference)
#include <cuda_runtime.h>
#include <cstdint>

#define P_NODES 20000
#define HID 128
#define POOLW 512

typedef unsigned long long u64;

// ---- packed f32x2 helpers (sm_103a FFMA2 path) ------------------------------
__device__ __forceinline__ u64 pack2(float lo, float hi) {
    u64 r; asm("mov.b64 %0, {%1, %2};" : "=l"(r) : "f"(lo), "f"(hi)); return r;
}
__device__ __forceinline__ u64 bcast2(float x) {
    u64 r; asm("mov.b64 %0, {%1, %1};" : "=l"(r) : "f"(x)); return r;
}
__device__ __forceinline__ void ffma2(u64 &d, u64 a, u64 b) {
    asm("fma.rn.f32x2 %0, %1, %2, %0;" : "+l"(d) : "l"(a), "l"(b));
}
__device__ __forceinline__ float2 unpack2(u64 v) {
    float lo, hi; asm("mov.b64 {%0, %1}, %2;" : "=f"(lo), "=f"(hi) : "l"(v));
    return make_float2(lo, hi);
}

// Scratch (static __device__ arrays — no runtime allocation).
__device__ __align__(16) float g_pool[P_NODES * POOLW];   // [P][512] concat: table,pred,agg,join
__device__ __align__(16) float g_cnt[4 * P_NODES];        // [type][P]
__device__ float g_scale[POOLW];
__device__ float g_shift[POOLW];

// ---------------------------------------------------------------- zero scratch
__global__ void zero_kernel() {
    int i = blockIdx.x * blockDim.x + threadIdx.x;
    const int n_pool4 = P_NODES * POOLW / 4;
    const int n_cnt4  = 4 * P_NODES / 4;
    float4 z = make_float4(0.f, 0.f, 0.f, 0.f);
    if (i < n_pool4) ((float4*)g_pool)[i] = z;
    else if (i < n_pool4 + n_cnt4) ((float4*)g_cnt)[i - n_pool4] = z;
}

// ------------------------------------------- fused encoder GEMM + segment scatter
// Tile: 128 rows x 128 cols, 256 threads, 8x8 micro-tile (f32x2 packed).
// K is chunked (KW<=64) so smem = 67,584 B -> 3 CTAs/SM for latency hiding.
#define ASTRIDE 68

template <int KW, int D>
__device__ __forceinline__ void enc_stage(
    float* __restrict__ Wsh, float* __restrict__ Ash,
    const float* __restrict__ feat, const float* __restrict__ W,
    int k0, int row0, int N, int tid)
{
    // W rows [k0, k0+KW) -> Wsh[KW][128]
    const float4* Wg = (const float4*)W;
    for (int i = tid; i < KW * 32; i += 256) {
        int r = i >> 5, q = i & 31;
        ((float4*)Wsh)[i] = Wg[(k0 + r) * 32 + q];
    }
    // A cols [k0, k0+KW) for 128 rows -> Ash[128][ASTRIDE]
    constexpr int RQ = KW / 4;
    const float4* Fg = (const float4*)feat;
    for (int i = tid; i < 128 * RQ; i += 256) {
        int r = i / RQ, q = i - r * RQ;
        int gr = row0 + r;
        float4 v = make_float4(0.f, 0.f, 0.f, 0.f);
        if (gr < N) v = Fg[(size_t)gr * (D / 4) + k0 / 4 + q];
        *(float4*)&Ash[r * ASTRIDE + q * 4] = v;
    }
}

template <int KW>
__device__ __forceinline__ void enc_compute(
    const float* __restrict__ Wsh, const float* __restrict__ Ash,
    u64 acc2[8][4], int tx, int ty)
{
    #pragma unroll 2
    for (int k = 0; k < KW; k++) {
        u64 ap[8];
        #pragma unroll
        for (int i = 0; i < 8; i++) ap[i] = bcast2(Ash[(ty * 8 + i) * ASTRIDE + k]);
        longlong2 wq0 = *(const longlong2*)&Wsh[k * HID + tx * 8];
        longlong2 wq1 = *(const longlong2*)&Wsh[k * HID + tx * 8 + 4];
        u64 wp[4] = {(u64)wq0.x, (u64)wq0.y, (u64)wq1.x, (u64)wq1.y};
        #pragma unroll
        for (int i = 0; i < 8; i++) {
            ffma2(acc2[i][0], ap[i], wp[0]);
            ffma2(acc2[i][1], ap[i], wp[1]);
            ffma2(acc2[i][2], ap[i], wp[2]);
            ffma2(acc2[i][3], ap[i], wp[3]);
        }
    }
}

template <int D>
__global__ void __launch_bounds__(256) enc_kernel(
    const float* __restrict__ feat, const int* __restrict__ idx,
    const float* __restrict__ W, const float* __restrict__ bias,
    int N, int toff)
{
    extern __shared__ float sh[];
    float* Wsh = sh;                   // [64][128]
    float* Ash = sh + 64 * HID;        // [128][ASTRIDE]
    const int tid = threadIdx.x;
    const int row0 = blockIdx.x * 128;
    const int tx = tid & 15, ty = tid >> 4;

    // Prefetch scatter indices for this thread's 8 rows (hide DRAM latency)
    int pidx[8];
    #pragma unroll
    for (int i = 0; i < 8; i++) {
        int gr = row0 + ty * 8 + i;
        pidx[i] = (gr < N) ? idx[gr] : -1;
    }

    u64 acc2[8][4];
    #pragma unroll
    for (int jj = 0; jj < 4; jj++) {
        u64 bp = pack2(__ldg(&bias[tx * 8 + 2 * jj]), __ldg(&bias[tx * 8 + 2 * jj + 1]));
        #pragma unroll
        for (int i = 0; i < 8; i++) acc2[i][jj] = bp;
    }

    constexpr int NFULL = D / 64;
    constexpr int TAIL  = D % 64;      // 0 or 32 for our shapes
    #pragma unroll
    for (int kc = 0; kc < NFULL; kc++) {
        enc_stage<64, D>(Wsh, Ash, feat, W, kc * 64, row0, N, tid);
        __syncthreads();
        enc_compute<64>(Wsh, Ash, acc2, tx, ty);
        __syncthreads();
    }
    if (TAIL) {
        enc_stage<(TAIL ? TAIL : 4), D>(Wsh, Ash, feat, W, NFULL * 64, row0, N, tid);
        __syncthreads();
        enc_compute<(TAIL ? TAIL : 4)>(Wsh, Ash, acc2, tx, ty);
        __syncthreads();
    }

    // Epilogue: ReLU + vector red into pooled concat buffer
    #pragma unroll
    for (int i = 0; i < 8; i++) {
        int p = pidx[i];
        if (p < 0) continue;
        float* dst = g_pool + (size_t)p * POOLW + toff * HID + tx * 8;
        float2 c0 = unpack2(acc2[i][0]), c1 = unpack2(acc2[i][1]);
        float2 c2 = unpack2(acc2[i][2]), c3 = unpack2(acc2[i][3]);
        float4 v0 = make_float4(fmaxf(c0.x, 0.f), fmaxf(c0.y, 0.f),
                                fmaxf(c1.x, 0.f), fmaxf(c1.y, 0.f));
        float4 v1 = make_float4(fmaxf(c2.x, 0.f), fmaxf(c2.y, 0.f),
                                fmaxf(c3.x, 0.f), fmaxf(c3.y, 0.f));
        atomicAdd((float4*)dst, v0);
        atomicAdd((float4*)(dst + 4), v1);
    }
    if (tid < 128) {
        int gr = row0 + tid;
        if (gr < N) atomicAdd(&g_cnt[toff * P_NODES + idx[gr]], 1.0f);
    }
}

// --------------------------------------------- BN batch stats -> scale/shift fold
__global__ void stats_kernel(const float* __restrict__ gamma,
                             const float* __restrict__ beta)
{
    const int c = blockIdx.x;        // 0..511
    const int t = c >> 7;            // type for the count denominator
    const int tid = threadIdx.x;
    double s = 0.0, s2 = 0.0;
    for (int p = tid; p < P_NODES; p += 256) {
        float cv = g_cnt[t * P_NODES + p];
        float x = g_pool[(size_t)p * POOLW + c] / fmaxf(cv, 1.0f);
        s += (double)x;
        s2 += (double)x * (double)x;
    }
    __shared__ double sh1[256], sh2[256];
    sh1[tid] = s; sh2[tid] = s2;
    __syncthreads();
    for (int off = 128; off > 0; off >>= 1) {
        if (tid < off) { sh1[tid] += sh1[tid + off]; sh2[tid] += sh2[tid + off]; }
        __syncthreads();
    }
    if (tid == 0) {
        double mu = sh1[0] / (double)P_NODES;
        double var = sh2[0] / (double)P_NODES - mu * mu;
        float sc = gamma[c] * rsqrtf((float)var + 1e-5f);
        g_scale[c] = sc;
        g_shift[c] = beta[c] - (float)mu * sc;
    }
}

// ------------------------------------------------ fused BN + 3-layer MLP head
// Block = 128 rows of the 20000-plan matrix; 256 threads; 8x8 micro-tile (f32x2).
__global__ void __launch_bounds__(256) mlp_kernel(
    const float* __restrict__ W1, const float* __restrict__ b1,
    const float* __restrict__ W2, const float* __restrict__ b2,
    const float* __restrict__ W3, const float* __restrict__ b3,
    float* __restrict__ out)
{
    extern __shared__ float sh[];
    float* Ax = sh;                    // [128][132]  (x chunk, later h2)
    float* Wc = Ax + 128 * 132;        // [128][128]  (W1 chunk, later W2)
    float* h1 = Wc + 128 * 128;        // [128][132]
    __shared__ float rcs[128];
    const int tid = threadIdx.x;
    const int tx = tid & 15, ty = tid >> 4;
    const int row0 = blockIdx.x * 128;

    u64 acc2[8][4];
    #pragma unroll
    for (int jj = 0; jj < 4; jj++) {
        u64 bp = pack2(__ldg(&b1[tx * 8 + 2 * jj]), __ldg(&b1[tx * 8 + 2 * jj + 1]));
        #pragma unroll
        for (int i = 0; i < 8; i++) acc2[i][jj] = bp;
    }

    // ---- layer 1: x_bn @ W1, k chunked by type (chunk kc == type kc)
    for (int kc = 0; kc < 4; kc++) {
        __syncthreads();
        if (tid < 128) {
            int p = row0 + tid;
            float cv = (p < P_NODES) ? g_cnt[kc * P_NODES + p] : 1.0f;
            rcs[tid] = 1.0f / fmaxf(cv, 1.0f);
        }
        __syncthreads();
        for (int i = tid; i < 128 * 32; i += 256) {
            int r = i >> 5, q = i & 31;
            int p = row0 + r;
            float4 v = make_float4(0.f, 0.f, 0.f, 0.f);
            if (p < P_NODES) {
                v = ((const float4*)g_pool)[(size_t)p * (POOLW / 4) + kc * 32 + q];
                float rc = rcs[r];
                int c0 = kc * 128 + q * 4;
                v.x = v.x * rc * g_scale[c0 + 0] + g_shift[c0 + 0];
                v.y = v.y * rc * g_scale[c0 + 1] + g_shift[c0 + 1];
                v.z = v.z * rc * g_scale[c0 + 2] + g_shift[c0 + 2];
                v.w = v.w * rc * g_scale[c0 + 3] + g_shift[c0 + 3];
            }
            *(float4*)&Ax[r * 132 + q * 4] = v;
        }
        for (int i = tid; i < 128 * 32; i += 256)
            ((float4*)Wc)[i] = ((const float4*)W1)[kc * 4096 + i];
        __syncthreads();
        #pragma unroll 2
        for (int k = 0; k < 128; k++) {
            u64 ap[8];
            #pragma unroll
            for (int i = 0; i < 8; i++) ap[i] = bcast2(Ax[(ty * 8 + i) * 132 + k]);
            longlong2 wq0 = *(const longlong2*)&Wc[k * 128 + tx * 8];
            longlong2 wq1 = *(const longlong2*)&Wc[k * 128 + tx * 8 + 4];
            u64 wp[4] = {(u64)wq0.x, (u64)wq0.y, (u64)wq1.x, (u64)wq1.y};
            #pragma unroll
            for (int i = 0; i < 8; i++) {
                ffma2(acc2[i][0], ap[i], wp[0]);
                ffma2(acc2[i][1], ap[i], wp[1]);
                ffma2(acc2[i][2], ap[i], wp[2]);
                ffma2(acc2[i][3], ap[i], wp[3]);
            }
        }
    }
    __syncthreads();

    // h1 = relu(acc); stage W2
    #pragma unroll
    for (int i = 0; i < 8; i++) {
        float2 c0 = unpack2(acc2[i][0]), c1 = unpack2(acc2[i][1]);
        float2 c2 = unpack2(acc2[i][2]), c3 = unpack2(acc2[i][3]);
        float4 v0 = make_float4(fmaxf(c0.x, 0.f), fmaxf(c0.y, 0.f),
                                fmaxf(c1.x, 0.f), fmaxf(c1.y, 0.f));
        float4 v1 = make_float4(fmaxf(c2.x, 0.f), fmaxf(c2.y, 0.f),
                                fmaxf(c3.x, 0.f), fmaxf(c3.y, 0.f));
        *(float4*)&h1[(ty * 8 + i) * 132 + tx * 8]     = v0;
        *(float4*)&h1[(ty * 8 + i) * 132 + tx * 8 + 4] = v1;
    }
    for (int i = tid; i < 128 * 32; i += 256)
        ((float4*)Wc)[i] = ((const float4*)W2)[i];
    __syncthreads();

    // ---- layer 2
    #pragma unroll
    for (int jj = 0; jj < 4; jj++) {
        u64 bp = pack2(__ldg(&b2[tx * 8 + 2 * jj]), __ldg(&b2[tx * 8 + 2 * jj + 1]));
        #pragma unroll
        for (int i = 0; i < 8; i++) acc2[i][jj] = bp;
    }
    #pragma unroll 2
    for (int k = 0; k < 128; k++) {
        u64 ap[8];
        #pragma unroll
        for (int i = 0; i < 8; i++) ap[i] = bcast2(h1[(ty * 8 + i) * 132 + k]);
        longlong2 wq0 = *(const longlong2*)&Wc[k * 128 + tx * 8];
        longlong2 wq1 = *(const longlong2*)&Wc[k * 128 + tx * 8 + 4];
        u64 wp[4] = {(u64)wq0.x, (u64)wq0.y, (u64)wq1.x, (u64)wq1.y};
        #pragma unroll
        for (int i = 0; i < 8; i++) {
            ffma2(acc2[i][0], ap[i], wp[0]);
            ffma2(acc2[i][1], ap[i], wp[1]);
            ffma2(acc2[i][2], ap[i], wp[2]);
            ffma2(acc2[i][3], ap[i], wp[3]);
        }
    }
    __syncthreads();
    // h2 = relu(acc) -> Ax
    #pragma unroll
    for (int i = 0; i < 8; i++) {
        float2 c0 = unpack2(acc2[i][0]), c1 = unpack2(acc2[i][1]);
        float2 c2 = unpack2(acc2[i][2]), c3 = unpack2(acc2[i][3]);
        float4 v0 = make_float4(fmaxf(c0.x, 0.f), fmaxf(c0.y, 0.f),
                                fmaxf(c1.x, 0.f), fmaxf(c1.y, 0.f));
        float4 v1 = make_float4(fmaxf(c2.x, 0.f), fmaxf(c2.y, 0.f),
                                fmaxf(c3.x, 0.f), fmaxf(c3.y, 0.f));
        *(float4*)&Ax[(ty * 8 + i) * 132 + tx * 8]     = v0;
        *(float4*)&Ax[(ty * 8 + i) * 132 + tx * 8 + 4] = v1;
    }
    __syncthreads();

    // ---- layer 3: out[p] = h2 . W3 + b3   (2 threads per row)
    {
        int r = tid >> 1, half = tid & 1;
        float s = 0.f;
        const float* h2row = &Ax[r * 132 + half * 64];
        #pragma unroll 8
        for (int i = 0; i < 64; i++) s += h2row[i] * __ldg(&W3[half * 64 + i]);
        s += __shfl_xor_sync(0xffffffffu, s, 1);
        int p = row0 + r;
        if (half == 0 && p < P_NODES) out[p] = s + __ldg(&b3[0]);
    }
}

// --------------------------------------------------------------------- launch
extern "C" void kernel_launch(void* const* d_in, const int* in_sizes, int n_in,
                              void* d_out, int out_size)
{
    // Resolve inputs by element count (+ stable relative order for equal sizes).
    const float *feat_t = 0, *feat_p = 0, *feat_a = 0, *feat_j = 0;
    const int   *idx_t = 0, *idx_p = 0, *idx_a = 0, *idx_j = 0;
    const float *W_t = 0, *W_p = 0, *W_a = 0, *W_j = 0;
    const float *bn_g = 0, *bn_b = 0, *W1 = 0, *W2 = 0;
    const float *f128[8] = {0};
    const float *f1[2] = {0};
    int n8192 = 0, n512 = 0, n128 = 0, n1 = 0;

    for (int i = 0; i < n_in; i++) {
        const float* p = (const float*)d_in[i];
        switch (in_sizes[i]) {
            case 64000000: feat_p = p; break;
            case 9600000:  feat_t = p; break;
            case 5120000:  feat_j = p; break;
            case 3840000:  feat_a = p; break;
            case 400000:   idx_p = (const int*)p; break;
            case 100000:   idx_t = (const int*)p; break;
            case 80000:    idx_j = (const int*)p; break;
            case 60000:    idx_a = (const int*)p; break;
            case 20480:    W_p = p; break;
            case 12288:    W_t = p; break;
            case 65536:    W1 = p; break;
            case 16384:    W2 = p; break;
            case 8192:     if (n8192++ == 0) W_a = p; else W_j = p; break;
            case 512:      if (n512++ == 0) bn_g = p; else bn_b = p; break;
            case 128:      if (n128 < 8) f128[n128] = p; n128++; break;
            case 1:        if (n1 < 2) f1[n1] = p; n1++; break;
            default: break;
        }
    }
    // 128-sized order (identical under signature or dict ordering):
    // b_table, b_pred, b_agg, b_join, b1, b2, W3
    const float *b_t = f128[0], *b_p = f128[1], *b_a = f128[2], *b_j = f128[3];
    const float *b1 = f128[4], *b2 = f128[5], *W3 = f128[6];
    const float *b3 = f1[0];
    float* out = (float*)d_out;

    const int ENC_SMEM = (64 * HID + 128 * ASTRIDE) * 4;   // 67,584 B
    cudaFuncSetAttribute(enc_kernel<160>, cudaFuncAttributeMaxDynamicSharedMemorySize, ENC_SMEM);
    cudaFuncSetAttribute(enc_kernel<96>,  cudaFuncAttributeMaxDynamicSharedMemorySize, ENC_SMEM);
    cudaFuncSetAttribute(enc_kernel<64>,  cudaFuncAttributeMaxDynamicSharedMemorySize, ENC_SMEM);
    cudaFuncSetAttribute(mlp_kernel,      cudaFuncAttributeMaxDynamicSharedMemorySize, 200704);

    zero_kernel<<<(P_NODES * POOLW / 4 + P_NODES + 255) / 256, 256>>>();

    enc_kernel<96><<<(100000 + 127) / 128, 256, ENC_SMEM>>>(feat_t, idx_t, W_t, b_t, 100000, 0);
    enc_kernel<160><<<(400000 + 127) / 128, 256, ENC_SMEM>>>(feat_p, idx_p, W_p, b_p, 400000, 1);
    enc_kernel<64><<<(60000 + 127) / 128, 256, ENC_SMEM>>>(feat_a, idx_a, W_a, b_a, 60000, 2);
    enc_kernel<64><<<(80000 + 127) / 128, 256, ENC_SMEM>>>(feat_j, idx_j, W_j, b_j, 80000, 3);

    stats_kernel<<<POOLW, 256>>>(bn_g, bn_b);

    mlp_kernel<<<(P_NODES + 127) / 128, 256, (128 * 132 + 128 * 128 + 128 * 132) * 4>>>(
        W1, b1, W2, b2, W3, b3, out);
}

// round 6
// speedup vs baseline: 1.5271x; 1.5271x over previous
#include <cuda_runtime.h>
#include <cstdint>

#define P_NODES 20000
#define HID 128
#define POOLW 512
#define KW 32
#define AST 36

typedef unsigned long long u64;

// ---- packed f32x2 helpers (sm_103a FFMA2 path) ------------------------------
__device__ __forceinline__ u64 pack2(float lo, float hi) {
    u64 r; asm("mov.b64 %0, {%1, %2};" : "=l"(r) : "f"(lo), "f"(hi)); return r;
}
__device__ __forceinline__ u64 bcast2(float x) {
    u64 r; asm("mov.b64 %0, {%1, %1};" : "=l"(r) : "f"(x)); return r;
}
__device__ __forceinline__ void ffma2(u64 &d, u64 a, u64 b) {
    asm("fma.rn.f32x2 %0, %1, %2, %0;" : "+l"(d) : "l"(a), "l"(b));
}
__device__ __forceinline__ float2 unpack2(u64 v) {
    float lo, hi; asm("mov.b64 {%0, %1}, %2;" : "=f"(lo), "=f"(hi) : "l"(v));
    return make_float2(lo, hi);
}

// ---- cp.async helpers -------------------------------------------------------
__device__ __forceinline__ uint32_t smem_u32(const void* p) {
    return (uint32_t)__cvta_generic_to_shared(p);
}
__device__ __forceinline__ void cp16(uint32_t dst, const void* src, int sz) {
    asm volatile("cp.async.cg.shared.global [%0], [%1], 16, %2;"
                 :: "r"(dst), "l"(src), "r"(sz));
}
__device__ __forceinline__ void cp_commit() {
    asm volatile("cp.async.commit_group;" ::: "memory");
}
template <int G>
__device__ __forceinline__ void cp_wait() {
    asm volatile("cp.async.wait_group %0;" :: "n"(G) : "memory");
}

// Scratch (static __device__ arrays — no runtime allocation).
__device__ __align__(16) float g_pool[P_NODES * POOLW];   // [P][512] concat: table,pred,agg,join
__device__ __align__(16) float g_cnt[4 * P_NODES];        // [type][P]
__device__ __align__(16) float g_sum[POOLW];
__device__ __align__(16) float g_sum2[POOLW];
__device__ float g_scale[POOLW];
__device__ float g_shift[POOLW];

// ---------------------------------------------------------------- zero scratch
__global__ void zero_kernel() {
    int i = blockIdx.x * blockDim.x + threadIdx.x;
    const int n_pool4 = P_NODES * POOLW / 4;
    const int n_cnt4  = 4 * P_NODES / 4;
    const int n_sum4  = 2 * POOLW / 4;
    float4 z = make_float4(0.f, 0.f, 0.f, 0.f);
    if (i < n_pool4) ((float4*)g_pool)[i] = z;
    else if (i < n_pool4 + n_cnt4) ((float4*)g_cnt)[i - n_pool4] = z;
    else if (i < n_pool4 + n_cnt4 + n_sum4) {
        int j = i - n_pool4 - n_cnt4;
        if (j < POOLW / 4) ((float4*)g_sum)[j] = z;
        else ((float4*)g_sum2)[j - POOLW / 4] = z;
    }
}

// ------------------------------------------- fused encoder GEMM + segment scatter
// 128x128 tile, 256 threads, 8x8 micro-tile (f32x2). cp.async double-buffered
// K-chunks of 32. smem = 69,632 B -> 2 CTAs/SM with regs capped at 128.
template <int D>
__device__ __forceinline__ void enc_stage_async(
    uint32_t wdst, uint32_t adst,
    const float* __restrict__ W, const float* __restrict__ feat,
    int k0, int row0, int N, int tid)
{
    #pragma unroll
    for (int j = 0; j < 4; j++) {           // W rows [k0,k0+32) -> [32][128]
        int o = tid + j * 256;
        int r = o >> 5, q = o & 31;
        cp16(wdst + (uint32_t)(r * 128 + q * 4) * 4, W + (k0 + r) * 128 + q * 4, 16);
    }
    #pragma unroll
    for (int j = 0; j < 4; j++) {           // A cols [k0,k0+32) -> [128][AST]
        int o = tid + j * 256;
        int r = o >> 3, s = o & 7;
        int gr = row0 + r;
        const float* src = feat + ((gr < N) ? ((size_t)gr * D + k0 + s * 4) : 0);
        cp16(adst + (uint32_t)(r * AST + s * 4) * 4, src, (gr < N) ? 16 : 0);
    }
}

__device__ __forceinline__ void enc_compute32(
    const float* __restrict__ Ws, const float* __restrict__ As,
    u64 acc2[8][4], int tx, int ty)
{
    #pragma unroll
    for (int k2 = 0; k2 < KW; k2 += 2) {
        u64 a01[8];
        #pragma unroll
        for (int i = 0; i < 8; i++)
            a01[i] = *(const u64*)&As[(ty * 8 + i) * AST + k2];
        longlong2 p0 = *(const longlong2*)&Ws[k2 * 128 + tx * 8];
        longlong2 p1 = *(const longlong2*)&Ws[k2 * 128 + tx * 8 + 4];
        longlong2 p2 = *(const longlong2*)&Ws[(k2 + 1) * 128 + tx * 8];
        longlong2 p3 = *(const longlong2*)&Ws[(k2 + 1) * 128 + tx * 8 + 4];
        u64 w0[4] = {(u64)p0.x, (u64)p0.y, (u64)p1.x, (u64)p1.y};
        u64 w1[4] = {(u64)p2.x, (u64)p2.y, (u64)p3.x, (u64)p3.y};
        #pragma unroll
        for (int i = 0; i < 8; i++) {
            float2 av = unpack2(a01[i]);
            u64 alo = bcast2(av.x), ahi = bcast2(av.y);
            ffma2(acc2[i][0], alo, w0[0]); ffma2(acc2[i][1], alo, w0[1]);
            ffma2(acc2[i][2], alo, w0[2]); ffma2(acc2[i][3], alo, w0[3]);
            ffma2(acc2[i][0], ahi, w1[0]); ffma2(acc2[i][1], ahi, w1[1]);
            ffma2(acc2[i][2], ahi, w1[2]); ffma2(acc2[i][3], ahi, w1[3]);
        }
    }
}

template <int D>
__global__ void __launch_bounds__(256, 2) enc_kernel(
    const float* __restrict__ feat, const int* __restrict__ idx,
    const float* __restrict__ W, const float* __restrict__ bias,
    int N, int toff)
{
    extern __shared__ float sh[];
    float* Wb[2] = { sh, sh + KW * 128 };
    float* Ab[2] = { sh + 2 * KW * 128, sh + 2 * KW * 128 + 128 * AST };
    const int tid = threadIdx.x;
    const int row0 = blockIdx.x * 128;
    const int tx = tid & 15, ty = tid >> 4;
    uint32_t wd[2] = { smem_u32(Wb[0]), smem_u32(Wb[1]) };
    uint32_t ad[2] = { smem_u32(Ab[0]), smem_u32(Ab[1]) };

    // Prefetch scatter indices (hide DRAM latency behind the GEMM)
    int pidx[8];
    #pragma unroll
    for (int i = 0; i < 8; i++) {
        int gr = row0 + ty * 8 + i;
        pidx[i] = (gr < N) ? idx[gr] : -1;
    }

    u64 acc2[8][4];
    #pragma unroll
    for (int jj = 0; jj < 4; jj++) {
        u64 bp = pack2(__ldg(&bias[tx * 8 + 2 * jj]), __ldg(&bias[tx * 8 + 2 * jj + 1]));
        #pragma unroll
        for (int i = 0; i < 8; i++) acc2[i][jj] = bp;
    }

    constexpr int NC = D / KW;
    enc_stage_async<D>(wd[0], ad[0], W, feat, 0, row0, N, tid);
    cp_commit();
    #pragma unroll
    for (int c = 0; c < NC; c++) {
        if (c + 1 < NC) {
            enc_stage_async<D>(wd[(c + 1) & 1], ad[(c + 1) & 1], W, feat,
                               (c + 1) * KW, row0, N, tid);
            cp_commit();
            cp_wait<1>();
        } else {
            cp_wait<0>();
        }
        __syncthreads();
        enc_compute32(Wb[c & 1], Ab[c & 1], acc2, tx, ty);
        __syncthreads();
    }

    // Epilogue: ReLU + vector red into pooled concat buffer
    #pragma unroll
    for (int i = 0; i < 8; i++) {
        int p = pidx[i];
        if (p < 0) continue;
        float* dst = g_pool + (size_t)p * POOLW + toff * HID + tx * 8;
        float2 c0 = unpack2(acc2[i][0]), c1 = unpack2(acc2[i][1]);
        float2 c2 = unpack2(acc2[i][2]), c3 = unpack2(acc2[i][3]);
        float4 v0 = make_float4(fmaxf(c0.x, 0.f), fmaxf(c0.y, 0.f),
                                fmaxf(c1.x, 0.f), fmaxf(c1.y, 0.f));
        float4 v1 = make_float4(fmaxf(c2.x, 0.f), fmaxf(c2.y, 0.f),
                                fmaxf(c3.x, 0.f), fmaxf(c3.y, 0.f));
        atomicAdd((float4*)dst, v0);
        atomicAdd((float4*)(dst + 4), v1);
    }
    if (tid < 128) {
        int gr = row0 + tid;
        if (gr < N) atomicAdd(&g_cnt[toff * P_NODES + idx[gr]], 1.0f);
    }
}

// --------------------------------------------- BN stats: coalesced partial sums
#define STATS_BLOCKS 160
#define STATS_CHUNK 125
__global__ void __launch_bounds__(256) stats_kernel() {
    const int tid = threadIdx.x;
    const int c0 = tid, c1 = tid + 256;
    const int t0 = c0 >> 7, t1 = c1 >> 7;
    const int pbeg = blockIdx.x * STATS_CHUNK;
    const int pend = min(pbeg + STATS_CHUNK, P_NODES);
    __shared__ float src[4][64];
    float s0 = 0.f, s20 = 0.f, s1 = 0.f, s21 = 0.f;

    for (int pt = pbeg; pt < pend; pt += 64) {
        // hoist reciprocal counts for this 64-row tile (one MUFU per (t,row))
        {
            int pr = tid & 63, t = tid >> 6;
            int p = pt + pr;
            src[t][pr] = (p < pend) ? 1.f / fmaxf(g_cnt[t * P_NODES + p], 1.f) : 0.f;
        }
        __syncthreads();
        int lim = min(64, pend - pt);
        for (int r = 0; r < lim; r++) {
            int p = pt + r;
            float x0 = g_pool[(size_t)p * POOLW + c0] * src[t0][r];
            float x1 = g_pool[(size_t)p * POOLW + c1] * src[t1][r];
            s0 += x0; s20 += x0 * x0;
            s1 += x1; s21 += x1 * x1;
        }
        __syncthreads();
    }
    atomicAdd(&g_sum[c0], s0);  atomicAdd(&g_sum2[c0], s20);
    atomicAdd(&g_sum[c1], s1);  atomicAdd(&g_sum2[c1], s21);
}

__global__ void finalize_kernel(const float* __restrict__ gamma,
                                const float* __restrict__ beta) {
    int c = blockIdx.x * blockDim.x + threadIdx.x;
    if (c < POOLW) {
        float mu = g_sum[c] * (1.f / P_NODES);
        float var = g_sum2[c] * (1.f / P_NODES) - mu * mu;
        float sc = gamma[c] * rsqrtf(var + 1e-5f);
        g_scale[c] = sc;
        g_shift[c] = beta[c] - mu * sc;
    }
}

// ------------------------------------------------ fused BN + 3-layer MLP head
__global__ void __launch_bounds__(256) mlp_kernel(
    const float* __restrict__ W1, const float* __restrict__ b1,
    const float* __restrict__ W2, const float* __restrict__ b2,
    const float* __restrict__ W3, const float* __restrict__ b3,
    float* __restrict__ out)
{
    extern __shared__ float sh[];
    float* Ax = sh;                    // [128][132]  (x chunk, later h2)
    float* Wc = Ax + 128 * 132;        // [128][128]  (W1 chunk, later W2)
    float* h1 = Wc + 128 * 128;        // [128][132]
    __shared__ float rcs[128];
    const int tid = threadIdx.x;
    const int tx = tid & 15, ty = tid >> 4;
    const int row0 = blockIdx.x * 128;

    u64 acc2[8][4];
    #pragma unroll
    for (int jj = 0; jj < 4; jj++) {
        u64 bp = pack2(__ldg(&b1[tx * 8 + 2 * jj]), __ldg(&b1[tx * 8 + 2 * jj + 1]));
        #pragma unroll
        for (int i = 0; i < 8; i++) acc2[i][jj] = bp;
    }

    // ---- layer 1: x_bn @ W1, k chunked by type (chunk kc == type kc)
    for (int kc = 0; kc < 4; kc++) {
        __syncthreads();
        if (tid < 128) {
            int p = row0 + tid;
            float cv = (p < P_NODES) ? g_cnt[kc * P_NODES + p] : 1.0f;
            rcs[tid] = 1.0f / fmaxf(cv, 1.0f);
        }
        __syncthreads();
        for (int i = tid; i < 128 * 32; i += 256) {
            int r = i >> 5, q = i & 31;
            int p = row0 + r;
            float4 v = make_float4(0.f, 0.f, 0.f, 0.f);
            if (p < P_NODES) {
                v = ((const float4*)g_pool)[(size_t)p * (POOLW / 4) + kc * 32 + q];
                float rc = rcs[r];
                int c0 = kc * 128 + q * 4;
                v.x = v.x * rc * g_scale[c0 + 0] + g_shift[c0 + 0];
                v.y = v.y * rc * g_scale[c0 + 1] + g_shift[c0 + 1];
                v.z = v.z * rc * g_scale[c0 + 2] + g_shift[c0 + 2];
                v.w = v.w * rc * g_scale[c0 + 3] + g_shift[c0 + 3];
            }
            *(float4*)&Ax[r * 132 + q * 4] = v;
        }
        for (int i = tid; i < 128 * 32; i += 256)
            ((float4*)Wc)[i] = ((const float4*)W1)[kc * 4096 + i];
        __syncthreads();
        #pragma unroll 2
        for (int k = 0; k < 128; k++) {
            u64 ap[8];
            #pragma unroll
            for (int i = 0; i < 8; i++) ap[i] = bcast2(Ax[(ty * 8 + i) * 132 + k]);
            longlong2 wq0 = *(const longlong2*)&Wc[k * 128 + tx * 8];
            longlong2 wq1 = *(const longlong2*)&Wc[k * 128 + tx * 8 + 4];
            u64 wp[4] = {(u64)wq0.x, (u64)wq0.y, (u64)wq1.x, (u64)wq1.y};
            #pragma unroll
            for (int i = 0; i < 8; i++) {
                ffma2(acc2[i][0], ap[i], wp[0]);
                ffma2(acc2[i][1], ap[i], wp[1]);
                ffma2(acc2[i][2], ap[i], wp[2]);
                ffma2(acc2[i][3], ap[i], wp[3]);
            }
        }
    }
    __syncthreads();

    // h1 = relu(acc); stage W2
    #pragma unroll
    for (int i = 0; i < 8; i++) {
        float2 c0 = unpack2(acc2[i][0]), c1 = unpack2(acc2[i][1]);
        float2 c2 = unpack2(acc2[i][2]), c3 = unpack2(acc2[i][3]);
        float4 v0 = make_float4(fmaxf(c0.x, 0.f), fmaxf(c0.y, 0.f),
                                fmaxf(c1.x, 0.f), fmaxf(c1.y, 0.f));
        float4 v1 = make_float4(fmaxf(c2.x, 0.f), fmaxf(c2.y, 0.f),
                                fmaxf(c3.x, 0.f), fmaxf(c3.y, 0.f));
        *(float4*)&h1[(ty * 8 + i) * 132 + tx * 8]     = v0;
        *(float4*)&h1[(ty * 8 + i) * 132 + tx * 8 + 4] = v1;
    }
    for (int i = tid; i < 128 * 32; i += 256)
        ((float4*)Wc)[i] = ((const float4*)W2)[i];
    __syncthreads();

    // ---- layer 2
    #pragma unroll
    for (int jj = 0; jj < 4; jj++) {
        u64 bp = pack2(__ldg(&b2[tx * 8 + 2 * jj]), __ldg(&b2[tx * 8 + 2 * jj + 1]));
        #pragma unroll
        for (int i = 0; i < 8; i++) acc2[i][jj] = bp;
    }
    #pragma unroll 2
    for (int k = 0; k < 128; k++) {
        u64 ap[8];
        #pragma unroll
        for (int i = 0; i < 8; i++) ap[i] = bcast2(h1[(ty * 8 + i) * 132 + k]);
        longlong2 wq0 = *(const longlong2*)&Wc[k * 128 + tx * 8];
        longlong2 wq1 = *(const longlong2*)&Wc[k * 128 + tx * 8 + 4];
        u64 wp[4] = {(u64)wq0.x, (u64)wq0.y, (u64)wq1.x, (u64)wq1.y};
        #pragma unroll
        for (int i = 0; i < 8; i++) {
            ffma2(acc2[i][0], ap[i], wp[0]);
            ffma2(acc2[i][1], ap[i], wp[1]);
            ffma2(acc2[i][2], ap[i], wp[2]);
            ffma2(acc2[i][3], ap[i], wp[3]);
        }
    }
    __syncthreads();
    // h2 = relu(acc) -> Ax
    #pragma unroll
    for (int i = 0; i < 8; i++) {
        float2 c0 = unpack2(acc2[i][0]), c1 = unpack2(acc2[i][1]);
        float2 c2 = unpack2(acc2[i][2]), c3 = unpack2(acc2[i][3]);
        float4 v0 = make_float4(fmaxf(c0.x, 0.f), fmaxf(c0.y, 0.f),
                                fmaxf(c1.x, 0.f), fmaxf(c1.y, 0.f));
        float4 v1 = make_float4(fmaxf(c2.x, 0.f), fmaxf(c2.y, 0.f),
                                fmaxf(c3.x, 0.f), fmaxf(c3.y, 0.f));
        *(float4*)&Ax[(ty * 8 + i) * 132 + tx * 8]     = v0;
        *(float4*)&Ax[(ty * 8 + i) * 132 + tx * 8 + 4] = v1;
    }
    __syncthreads();

    // ---- layer 3: out[p] = h2 . W3 + b3   (2 threads per row)
    {
        int r = tid >> 1, half = tid & 1;
        float s = 0.f;
        const float* h2row = &Ax[r * 132 + half * 64];
        #pragma unroll 8
        for (int i = 0; i < 64; i++) s += h2row[i] * __ldg(&W3[half * 64 + i]);
        s += __shfl_xor_sync(0xffffffffu, s, 1);
        int p = row0 + r;
        if (half == 0 && p < P_NODES) out[p] = s + __ldg(&b3[0]);
    }
}

// --------------------------------------------------------------------- launch
extern "C" void kernel_launch(void* const* d_in, const int* in_sizes, int n_in,
                              void* d_out, int out_size)
{
    const float *feat_t = 0, *feat_p = 0, *feat_a = 0, *feat_j = 0;
    const int   *idx_t = 0, *idx_p = 0, *idx_a = 0, *idx_j = 0;
    const float *W_t = 0, *W_p = 0, *W_a = 0, *W_j = 0;
    const float *bn_g = 0, *bn_b = 0, *W1 = 0, *W2 = 0;
    const float *f128[8] = {0};
    const float *f1[2] = {0};
    int n8192 = 0, n512 = 0, n128 = 0, n1 = 0;

    for (int i = 0; i < n_in; i++) {
        const float* p = (const float*)d_in[i];
        switch (in_sizes[i]) {
            case 64000000: feat_p = p; break;
            case 9600000:  feat_t = p; break;
            case 5120000:  feat_j = p; break;
            case 3840000:  feat_a = p; break;
            case 400000:   idx_p = (const int*)p; break;
            case 100000:   idx_t = (const int*)p; break;
            case 80000:    idx_j = (const int*)p; break;
            case 60000:    idx_a = (const int*)p; break;
            case 20480:    W_p = p; break;
            case 12288:    W_t = p; break;
            case 65536:    W1 = p; break;
            case 16384:    W2 = p; break;
            case 8192:     if (n8192++ == 0) W_a = p; else W_j = p; break;
            case 512:      if (n512++ == 0) bn_g = p; else bn_b = p; break;
            case 128:      if (n128 < 8) f128[n128] = p; n128++; break;
            case 1:        if (n1 < 2) f1[n1] = p; n1++; break;
            default: break;
        }
    }
    // 128-sized order: b_table, b_pred, b_agg, b_join, b1, b2, W3
    const float *b_t = f128[0], *b_p = f128[1], *b_a = f128[2], *b_j = f128[3];
    const float *b1 = f128[4], *b2 = f128[5], *W3 = f128[6];
    const float *b3 = f1[0];
    float* out = (float*)d_out;

    const int ENC_SMEM = (2 * KW * HID + 2 * 128 * AST) * 4;   // 69,632 B
    cudaFuncSetAttribute(enc_kernel<160>, cudaFuncAttributeMaxDynamicSharedMemorySize, ENC_SMEM);
    cudaFuncSetAttribute(enc_kernel<96>,  cudaFuncAttributeMaxDynamicSharedMemorySize, ENC_SMEM);
    cudaFuncSetAttribute(enc_kernel<64>,  cudaFuncAttributeMaxDynamicSharedMemorySize, ENC_SMEM);
    cudaFuncSetAttribute(mlp_kernel,      cudaFuncAttributeMaxDynamicSharedMemorySize, 200704);

    const int ZN = P_NODES * POOLW / 4 + P_NODES + 2 * POOLW / 4;
    zero_kernel<<<(ZN + 255) / 256, 256>>>();

    enc_kernel<96><<<(100000 + 127) / 128, 256, ENC_SMEM>>>(feat_t, idx_t, W_t, b_t, 100000, 0);
    enc_kernel<160><<<(400000 + 127) / 128, 256, ENC_SMEM>>>(feat_p, idx_p, W_p, b_p, 400000, 1);
    enc_kernel<64><<<(60000 + 127) / 128, 256, ENC_SMEM>>>(feat_a, idx_a, W_a, b_a, 60000, 2);
    enc_kernel<64><<<(80000 + 127) / 128, 256, ENC_SMEM>>>(feat_j, idx_j, W_j, b_j, 80000, 3);

    stats_kernel<<<STATS_BLOCKS, 256>>>();
    finalize_kernel<<<2, 256>>>(bn_g, bn_b);

    mlp_kernel<<<(P_NODES + 127) / 128, 256, (128 * 132 + 128 * 128 + 128 * 132) * 4>>>(
        W1, b1, W2, b2, W3, b3, out);
}